// round 13
// baseline (speedup 1.0000x reference)
#include <cuda_runtime.h>
#include <cuda_fp16.h>
#include <cstdint>
#include <math.h>

#define Bsz 32
#define Tn  128
#define Nn  47
#define CIN 192
#define COUT 256
#define KK  3

#define NT   512          // threads per block (16 warps)

#define XS_PITCH 200      // halves per t-row (192 + pad)
#define XS_BYTES (128 * XS_PITCH * 2)     // 51200
#define BS_PITCH 24       // halves per col-row (16 k + pad), 48B rows (16B-aligned)
#define BS_STAGE (512 * BS_PITCH * 2)     // 24576
#define OFF_BS   XS_BYTES                 // 51200
#define SMEM_TOTAL (XS_BYTES + 2 * BS_STAGE)   // 100352

#define HBUF_PITCH 264    // halves per t-row of fp16 hbuf (aliases xs/bs after mainloop)
#define OFF_PART   69632  // float[128][8][2] = 8192B (inside dead bs region)
#define OFF_LNSTAT 77824  // float[128][2] = 1024B

// ---------------- scratch ----------------
__device__ __align__(256) __half g_wh[(size_t)Nn * 512 * CIN];  // [n][j][c]

// ---------------- K1: rowsum (in-block) + fused fp16 weights, 8-wide ----------------
__global__ void __launch_bounds__(256) k_wh(const float* __restrict__ A, const float* __restrict__ adj,
                                            const float* __restrict__ dw, const float* __restrict__ Wpw,
                                            const float* __restrict__ Wres) {
    __shared__ float srs[KK][2];
    const int idx8_0 = blockIdx.x * 256;
    const int n0 = idx8_0 / (24 * 512);
    const int warp = threadIdx.x >> 5, lane = threadIdx.x & 31;
    if (warp < 6) {
        int k = warp % KK, nn = n0 + warp / KK;
        if (nn < Nn) {
            const float* ar = A   + ((size_t)k * Nn + nn) * Nn;
            const float* rr = adj + ((size_t)k * Nn + nn) * Nn;
            float s = 0.f, sa = 0.f;
            for (int m = lane; m < Nn; m += 32) {
                float v = ar[m] + 0.3f * tanhf(rr[m]);
                s += v; sa += fabsf(v);
            }
#pragma unroll
            for (int o = 16; o; o >>= 1) {
                s  += __shfl_xor_sync(0xFFFFFFFFu, s,  o);
                sa += __shfl_xor_sync(0xFFFFFFFFu, sa, o);
            }
            if (lane == 0) srs[k][warp / KK] = s / fmaxf(sa, 1.0f);
        }
    }
    __syncthreads();

    const int idx8 = idx8_0 + threadIdx.x;
    if (idx8 >= Nn * 512 * 24) return;
    const int c0 = (idx8 % 24) * 8;
    const int j  = (idx8 / 24) & 511;
    const int n  = idx8 / (24 * 512);
    float w8[8];
    if (j < COUT) {
#pragma unroll
        for (int i = 0; i < 8; i++) w8[i] = 0.f;
#pragma unroll
        for (int k = 0; k < KK; k++) {
            float rs = srs[k][n - n0];
            const float* dwp = dw + k * CIN + c0;
            const float* wp  = Wpw + (size_t)j * (KK * CIN) + k * CIN + c0;
            float4 d0 = *(const float4*)dwp, d1 = *(const float4*)(dwp + 4);
            float4 p0 = *(const float4*)wp,  p1 = *(const float4*)(wp + 4);
            w8[0] += rs * d0.x * p0.x; w8[1] += rs * d0.y * p0.y;
            w8[2] += rs * d0.z * p0.z; w8[3] += rs * d0.w * p0.w;
            w8[4] += rs * d1.x * p1.x; w8[5] += rs * d1.y * p1.y;
            w8[6] += rs * d1.z * p1.z; w8[7] += rs * d1.w * p1.w;
        }
    } else {
        const float* rp = Wres + (size_t)(j - COUT) * CIN + c0;
        float4 r0 = *(const float4*)rp, r1 = *(const float4*)(rp + 4);
        w8[0] = r0.x; w8[1] = r0.y; w8[2] = r0.z; w8[3] = r0.w;
        w8[4] = r1.x; w8[5] = r1.y; w8[6] = r1.z; w8[7] = r1.w;
    }
    __half2 h2[4];
#pragma unroll
    for (int i = 0; i < 4; i++) h2[i] = __floats2half2_rn(w8[2 * i], w8[2 * i + 1]);
    *(uint4*)(g_wh + (size_t)idx8 * 8) = *(const uint4*)h2;
}

// ---------------- helpers ----------------
__device__ __forceinline__ void cp_async16(uint32_t dst, const void* src) {
    asm volatile("cp.async.cg.shared.global [%0], [%1], 16;\n" :: "r"(dst), "l"(src));
}
__device__ __forceinline__ void mma16816(float* d, const uint32_t* a, const uint32_t* b) {
    asm volatile(
        "mma.sync.aligned.m16n8k16.row.col.f32.f16.f16.f32 "
        "{%0,%1,%2,%3}, {%4,%5,%6,%7}, {%8,%9}, {%0,%1,%2,%3};\n"
        : "+f"(d[0]), "+f"(d[1]), "+f"(d[2]), "+f"(d[3])
        : "r"(a[0]), "r"(a[1]), "r"(a[2]), "r"(a[3]), "r"(b[0]), "r"(b[1]));
}
__device__ __forceinline__ void ldsm_x4(uint32_t& r0, uint32_t& r1, uint32_t& r2, uint32_t& r3,
                                        uint32_t addr) {
    asm volatile("ldmatrix.sync.aligned.m8n8.x4.shared.b16 {%0,%1,%2,%3}, [%4];"
                 : "=r"(r0), "=r"(r1), "=r"(r2), "=r"(r3) : "r"(addr));
}
// branch-free GELU: Abramowitz-Stegun 7.1.26 erf (|err| <= 1.5e-7)
__device__ __forceinline__ float gelu_fast(float v) {
    float x  = v * 0.70710678118654752f;
    float ax = fabsf(x);
    float t  = __fdividef(1.0f, fmaf(0.3275911f, ax, 1.0f));
    float p  = fmaf(fmaf(fmaf(fmaf(1.061405429f, t, -1.453152027f), t, 1.421413741f),
                         t, -0.284496736f), t, 0.254829592f);
    float e  = __expf(-ax * ax);
    float er = fmaf(-p * t, e, 1.0f);
    er = copysignf(er, x);
    return 0.5f * v * (1.0f + er);
}

// ---------------- K2: fused per-(b,n) block; single-pass N=512; 2 CTAs/SM ----------------
__global__ void __launch_bounds__(NT, 2)
k_fused(const float* __restrict__ x, const float* __restrict__ convw,
        const float* __restrict__ gng, const float* __restrict__ gnb,
        const float* __restrict__ lng, const float* __restrict__ lnb,
        float* __restrict__ out) {
    extern __shared__ char sm[];
    __half* xs   = (__half*)sm;                       // [128][200] halves (dead after mainloop)
    __half* hb   = (__half*)sm;                       // [128][264] halves (aliases xs+bs0)
    float* part   = (float*)(sm + OFF_PART);          // [128][8][2]
    float* lnstat = (float*)(sm + OFF_LNSTAT);        // [128][2]
    __shared__ float s_gn[16][2];
    __shared__ float chA[256], chB[256];

    const int n = blockIdx.x, b = blockIdx.y;
    const int tid  = threadIdx.x;
    const int lane = tid & 31, warp = tid >> 5;
    const int g = lane >> 2, q = lane & 3;
    const int wm = warp & 1, wn = warp >> 1;          // 2 x 8 warp grid; warp tile 64t x 64c

    const __half* wbase = g_wh + (size_t)n * 512 * CIN;

    const uint32_t xs_u32 = (uint32_t)__cvta_generic_to_shared(xs);
    const uint32_t bs_u32 = xs_u32 + OFF_BS;

    // A ldmatrix addrs (4 m-tiles of 16 rows)
    const int a_row_off = (lane & 7) + ((lane >> 3) & 1) * 8;
    const int a_k_off   = ((lane >> 4) & 1) * 8;
    uint32_t addrA[4];
#pragma unroll
    for (int mi = 0; mi < 4; mi++)
        addrA[mi] = xs_u32 + (uint32_t)((wm * 64 + mi * 16 + a_row_off) * (XS_PITCH * 2) + a_k_off * 2);
    // B ldmatrix addrs: group0 = h cols (wn*32 + lane), group1 = res cols (256 + wn*32 + lane)
    uint32_t addrB0 = bs_u32 + (uint32_t)((wn * 32 + lane) * (BS_PITCH * 2));
    uint32_t addrB1 = bs_u32 + (uint32_t)((256 + wn * 32 + lane) * (BS_PITCH * 2));

    // stage one 16-k chunk of all 512 B cols; 1 col / thread, 32B = 2 cp.async
    auto stage = [&](int kc, int buf) {
        const __half* src = wbase + (size_t)tid * CIN + kc * 16;
        uint32_t d = bs_u32 + (uint32_t)(buf * BS_STAGE + tid * (BS_PITCH * 2));
        cp_async16(d,      src);
        cp_async16(d + 16, src + 8);
        asm volatile("cp.async.commit_group;\n");
    };

    // ---- load x tile -> fp16 smem (overlap with first B stage) ----
    stage(0, 0);
    for (int i = tid; i < 128 * 48; i += NT) {
        int t = i / 48, c4 = (i % 48) * 4;
        float4 v = *(const float4*)(x + ((size_t)(b * Tn + t) * Nn + n) * CIN + c4);
        __half2* dst = (__half2*)(xs + t * XS_PITCH + c4);
        dst[0] = __floats2half2_rn(v.x, v.y);
        dst[1] = __floats2half2_rn(v.z, v.w);
    }
    __syncthreads();

    float acc[4][8][4];
#pragma unroll
    for (int mi = 0; mi < 4; mi++)
#pragma unroll
        for (int ni = 0; ni < 8; ni++)
#pragma unroll
            for (int r = 0; r < 4; r++) acc[mi][ni][r] = 0.f;

    // ================= single mainloop: 12 chunks of 16-k, N=512 =================
#pragma unroll 1
    for (int kc = 0; kc < 12; kc++) {
        if (kc < 11) {
            stage(kc + 1, (kc + 1) & 1);
            asm volatile("cp.async.wait_group 1;\n");
        } else {
            asm volatile("cp.async.wait_group 0;\n");
        }
        __syncthreads();
        const uint32_t bsel = (uint32_t)((kc & 1) * BS_STAGE);
        const uint32_t kbb  = (uint32_t)(kc * 32);   // 16 k * 2B into A rows
        uint32_t afr[4][4];
        uint32_t bfr[8][2];
#pragma unroll
        for (int mi = 0; mi < 4; mi++)
            ldsm_x4(afr[mi][0], afr[mi][1], afr[mi][2], afr[mi][3], addrA[mi] + kbb);
        ldsm_x4(bfr[0][0], bfr[1][0], bfr[2][0], bfr[3][0], addrB0 + bsel);
        ldsm_x4(bfr[0][1], bfr[1][1], bfr[2][1], bfr[3][1], addrB0 + bsel + 16);
        ldsm_x4(bfr[4][0], bfr[5][0], bfr[6][0], bfr[7][0], addrB1 + bsel);
        ldsm_x4(bfr[4][1], bfr[5][1], bfr[6][1], bfr[7][1], addrB1 + bsel + 16);
#pragma unroll
        for (int ni = 0; ni < 8; ni++)
#pragma unroll
            for (int mi = 0; mi < 4; mi++)
                mma16816(acc[mi][ni], afr[mi], bfr[ni]);
        __syncthreads();
    }

    // ---- epilogue: write h (ni 0..3) into hb[t][c] fp16 (aliases dead xs/bs0) ----
#pragma unroll
    for (int mi = 0; mi < 4; mi++) {
#pragma unroll
        for (int half = 0; half < 2; half++) {
            int t = wm * 64 + mi * 16 + g + half * 8;
            int r = half * 2;
#pragma unroll
            for (int ni = 0; ni < 4; ni++) {
                int o0 = wn * 32 + ni * 8 + 2 * q;
                *(__half2*)(hb + t * HBUF_PITCH + o0) = __floats2half2_rn(acc[mi][ni][r], acc[mi][ni][r + 1]);
            }
        }
    }
    __syncthreads();

    // ---- temporal conv + GN stats; thread = (channel, t-half) ----
    const int o = tid & 255, hf = tid >> 8;
    const int ct0 = hf * 64, ct1 = ct0 + 64;
    const float w0 = convw[o * 3], w1 = convw[o * 3 + 1], w2 = convw[o * 3 + 2];
    float cprev = (ct0 == 0) ? 0.f : __half2float(hb[(ct0 - 1) * HBUF_PITCH + o]);
    float ccur  = __half2float(hb[ct0 * HBUF_PITCH + o]);
    float cbnd  = (ct1 == Tn) ? 0.f : __half2float(hb[ct1 * HBUF_PITCH + o]);
    __syncthreads();
    float cs = 0.f, cs2 = 0.f;
#pragma unroll 4
    for (int t = ct0; t < ct1; t++) {
        float nxt = (t == ct1 - 1) ? cbnd : __half2float(hb[(t + 1) * HBUF_PITCH + o]);
        float v = w0 * cprev + w1 * ccur + w2 * nxt;
        hb[t * HBUF_PITCH + o] = __float2half_rn(v);
        cs += v; cs2 += v * v;
        cprev = ccur; ccur = nxt;
    }
#pragma unroll
    for (int off = 16; off; off >>= 1) {
        cs  += __shfl_xor_sync(0xFFFFFFFFu, cs,  off);
        cs2 += __shfl_xor_sync(0xFFFFFFFFu, cs2, off);
    }
    if (lane == 0) { s_gn[warp][0] = cs; s_gn[warp][1] = cs2; }
    __syncthreads();
    if (hf == 0) {
        const int grp = warp & 7;
        float gs  = s_gn[grp][0] + s_gn[grp + 8][0];
        float gs2 = s_gn[grp][1] + s_gn[grp + 8][1];
        const float inv = 1.f / (32.f * Tn);
        float mu = gs * inv;
        float var = gs2 * inv - mu * mu;
        float rstd = rsqrtf(var + 1e-5f);
        float ga = gng[o] * rstd;
        chA[o] = ga;
        chB[o] = gnb[o] - mu * ga;
    }
    __syncthreads();

    // ---- fold: v = h*ga + gb + res (res = acc ni 4..7) + LN partial sums ----
#pragma unroll
    for (int mi = 0; mi < 4; mi++) {
#pragma unroll
        for (int half = 0; half < 2; half++) {
            int t = wm * 64 + mi * 16 + g + half * 8;
            int r = half * 2;
            float su = 0.f, sq = 0.f;
#pragma unroll
            for (int ni = 4; ni < 8; ni++) {
                int o0 = wn * 32 + (ni - 4) * 8 + 2 * q;
                __half2 hh = *(const __half2*)(hb + t * HBUF_PITCH + o0);
                float2 hv = __half22float2(hh);
                float v0 = hv.x * chA[o0]     + chB[o0]     + acc[mi][ni][r];
                float v1 = hv.y * chA[o0 + 1] + chB[o0 + 1] + acc[mi][ni][r + 1];
                acc[mi][ni][r] = v0; acc[mi][ni][r + 1] = v1;
                su += v0 + v1; sq += v0 * v0 + v1 * v1;
            }
            su += __shfl_xor_sync(0xFFFFFFFFu, su, 1);
            su += __shfl_xor_sync(0xFFFFFFFFu, su, 2);
            sq += __shfl_xor_sync(0xFFFFFFFFu, sq, 1);
            sq += __shfl_xor_sync(0xFFFFFFFFu, sq, 2);
            if (q == 0) *(float2*)(part + (t * 8 + wn) * 2) = make_float2(su, sq);
        }
    }
    __syncthreads();
    if (tid < Tn) {
        float su = 0.f, sq = 0.f;
#pragma unroll
        for (int w = 0; w < 8; w++) {
            float2 p = *(const float2*)(part + (tid * 8 + w) * 2);
            su += p.x; sq += p.y;
        }
        float mu = su * (1.f / 256.f);
        float var = sq * (1.f / 256.f) - mu * mu;
        *(float2*)(lnstat + tid * 2) = make_float2(mu, rsqrtf(var + 1e-5f));
    }
    __syncthreads();

    // ---- apply LN + GELU, direct store ----
    float2 lg2[4], lb2[4];
#pragma unroll
    for (int ni = 0; ni < 4; ni++) {
        int o0 = wn * 32 + ni * 8 + 2 * q;
        lg2[ni] = *(const float2*)(lng + o0);
        lb2[ni] = *(const float2*)(lnb + o0);
    }
#pragma unroll
    for (int mi = 0; mi < 4; mi++) {
#pragma unroll
        for (int half = 0; half < 2; half++) {
            int t = wm * 64 + mi * 16 + g + half * 8;
            float2 st = *(const float2*)(lnstat + t * 2);
            float mu = st.x, rs = st.y;
            float* ob = out + ((size_t)(b * Tn + t) * Nn + n) * COUT;
            int r = half * 2;
#pragma unroll
            for (int ni = 4; ni < 8; ni++) {
                int o0 = wn * 32 + (ni - 4) * 8 + 2 * q;
                float y0 = (acc[mi][ni][r]     - mu) * rs * lg2[ni - 4].x + lb2[ni - 4].x;
                float y1 = (acc[mi][ni][r + 1] - mu) * rs * lg2[ni - 4].y + lb2[ni - 4].y;
                *(float2*)(ob + o0) = make_float2(gelu_fast(y0), gelu_fast(y1));
            }
        }
    }
}

// ---------------- launch ----------------
extern "C" void kernel_launch(void* const* d_in, const int* in_sizes, int n_in,
                              void* d_out, int out_size) {
    const float* x     = (const float*)d_in[0];
    const float* A     = (const float*)d_in[1];
    const float* dw    = (const float*)d_in[2];
    const float* adj   = (const float*)d_in[3];
    const float* Wpw   = (const float*)d_in[4];
    const float* convw = (const float*)d_in[5];
    const float* gng   = (const float*)d_in[6];
    const float* gnb   = (const float*)d_in[7];
    const float* lng   = (const float*)d_in[8];
    const float* lnb   = (const float*)d_in[9];
    const float* Wres  = (const float*)d_in[10];
    float* out = (float*)d_out;

    cudaFuncSetAttribute(k_fused, cudaFuncAttributeMaxDynamicSharedMemorySize, SMEM_TOTAL);

    int total8 = Nn * 512 * 24;
    k_wh<<<(total8 + 255) / 256, 256>>>(A, adj, dw, Wpw, Wres);
    k_fused<<<dim3(Nn, Bsz), NT, SMEM_TOTAL>>>(x, convw, gng, gnb, lng, lnb, out);
}

// round 14
// speedup vs baseline: 3.0579x; 3.0579x over previous
#include <cuda_runtime.h>
#include <cuda_fp16.h>
#include <cstdint>
#include <math.h>

#define Bsz 32
#define Tn  128
#define Nn  47
#define CIN 192
#define COUT 256
#define KK  3

#define NT   512          // threads per block (16 warps)

#define XS_PITCH 200      // halves per t-row (192 + pad)
#define XS_BYTES (128 * XS_PITCH * 2)       // 51200
#define HBUF_PITCH 264    // halves per t-row (256 + pad)
#define HB_BYTES (128 * HBUF_PITCH * 2)     // 67584
#define OFF_HB   XS_BYTES                   // 51200
#define OFF_BS   (OFF_HB + HB_BYTES)        // 118784
#define BS_PITCH 72       // halves per col-row (64 k + 8 pad) = 144 B
#define BS_STAGE (256 * BS_PITCH * 2)       // 36864
#define SMEM_TOTAL (OFF_BS + 2 * BS_STAGE)  // 192512

#define OFF_PART   OFF_BS                   // float[128][8][2] = 8192 B (bs dead by fold)
#define OFF_LNSTAT (OFF_BS + 8192)          // float[128][2]

// ---------------- scratch ----------------
__device__ __align__(256) __half g_wh[(size_t)Nn * 512 * CIN];  // [n][j][c]

// ---------------- K1: rowsum (in-block) + fused fp16 weights, 8-wide ----------------
__global__ void __launch_bounds__(256) k_wh(const float* __restrict__ A, const float* __restrict__ adj,
                                            const float* __restrict__ dw, const float* __restrict__ Wpw,
                                            const float* __restrict__ Wres) {
    __shared__ float srs[KK][2];
    const int idx8_0 = blockIdx.x * 256;
    const int n0 = idx8_0 / (24 * 512);
    const int warp = threadIdx.x >> 5, lane = threadIdx.x & 31;
    if (warp < 6) {
        int k = warp % KK, nn = n0 + warp / KK;
        if (nn < Nn) {
            const float* ar = A   + ((size_t)k * Nn + nn) * Nn;
            const float* rr = adj + ((size_t)k * Nn + nn) * Nn;
            float s = 0.f, sa = 0.f;
            for (int m = lane; m < Nn; m += 32) {
                float v = ar[m] + 0.3f * tanhf(rr[m]);
                s += v; sa += fabsf(v);
            }
#pragma unroll
            for (int o = 16; o; o >>= 1) {
                s  += __shfl_xor_sync(0xFFFFFFFFu, s,  o);
                sa += __shfl_xor_sync(0xFFFFFFFFu, sa, o);
            }
            if (lane == 0) srs[k][warp / KK] = s / fmaxf(sa, 1.0f);
        }
    }
    __syncthreads();

    const int idx8 = idx8_0 + threadIdx.x;
    if (idx8 >= Nn * 512 * 24) return;
    const int c0 = (idx8 % 24) * 8;
    const int j  = (idx8 / 24) & 511;
    const int n  = idx8 / (24 * 512);
    float w8[8];
    if (j < COUT) {
#pragma unroll
        for (int i = 0; i < 8; i++) w8[i] = 0.f;
#pragma unroll
        for (int k = 0; k < KK; k++) {
            float rs = srs[k][n - n0];
            const float* dwp = dw + k * CIN + c0;
            const float* wp  = Wpw + (size_t)j * (KK * CIN) + k * CIN + c0;
            float4 d0 = *(const float4*)dwp, d1 = *(const float4*)(dwp + 4);
            float4 p0 = *(const float4*)wp,  p1 = *(const float4*)(wp + 4);
            w8[0] += rs * d0.x * p0.x; w8[1] += rs * d0.y * p0.y;
            w8[2] += rs * d0.z * p0.z; w8[3] += rs * d0.w * p0.w;
            w8[4] += rs * d1.x * p1.x; w8[5] += rs * d1.y * p1.y;
            w8[6] += rs * d1.z * p1.z; w8[7] += rs * d1.w * p1.w;
        }
    } else {
        const float* rp = Wres + (size_t)(j - COUT) * CIN + c0;
        float4 r0 = *(const float4*)rp, r1 = *(const float4*)(rp + 4);
        w8[0] = r0.x; w8[1] = r0.y; w8[2] = r0.z; w8[3] = r0.w;
        w8[4] = r1.x; w8[5] = r1.y; w8[6] = r1.z; w8[7] = r1.w;
    }
    __half2 h2[4];
#pragma unroll
    for (int i = 0; i < 4; i++) h2[i] = __floats2half2_rn(w8[2 * i], w8[2 * i + 1]);
    *(uint4*)(g_wh + (size_t)idx8 * 8) = *(const uint4*)h2;
}

// ---------------- helpers ----------------
__device__ __forceinline__ void cp_async16(uint32_t dst, const void* src) {
    asm volatile("cp.async.cg.shared.global [%0], [%1], 16;\n" :: "r"(dst), "l"(src));
}
__device__ __forceinline__ void mma16816(float* d, const uint32_t* a, const uint32_t* b) {
    asm volatile(
        "mma.sync.aligned.m16n8k16.row.col.f32.f16.f16.f32 "
        "{%0,%1,%2,%3}, {%4,%5,%6,%7}, {%8,%9}, {%0,%1,%2,%3};\n"
        : "+f"(d[0]), "+f"(d[1]), "+f"(d[2]), "+f"(d[3])
        : "r"(a[0]), "r"(a[1]), "r"(a[2]), "r"(a[3]), "r"(b[0]), "r"(b[1]));
}
__device__ __forceinline__ void ldsm_x4(uint32_t& r0, uint32_t& r1, uint32_t& r2, uint32_t& r3,
                                        uint32_t addr) {
    asm volatile("ldmatrix.sync.aligned.m8n8.x4.shared.b16 {%0,%1,%2,%3}, [%4];"
                 : "=r"(r0), "=r"(r1), "=r"(r2), "=r"(r3) : "r"(addr));
}
// branch-free GELU: Abramowitz-Stegun 7.1.26 erf (|err| <= 1.5e-7)
__device__ __forceinline__ float gelu_fast(float v) {
    float x  = v * 0.70710678118654752f;
    float ax = fabsf(x);
    float t  = __fdividef(1.0f, fmaf(0.3275911f, ax, 1.0f));
    float p  = fmaf(fmaf(fmaf(fmaf(1.061405429f, t, -1.453152027f), t, 1.421413741f),
                         t, -0.284496736f), t, 0.254829592f);
    float e  = __expf(-ax * ax);
    float er = fmaf(-p * t, e, 1.0f);
    er = copysignf(er, x);
    return 0.5f * v * (1.0f + er);
}

// ---------------- K2: fused per-(b,n) block; 64-k chunks; fp16 hbuf ----------------
__global__ void __launch_bounds__(NT, 1)
k_fused(const float* __restrict__ x, const float* __restrict__ convw,
        const float* __restrict__ gng, const float* __restrict__ gnb,
        const float* __restrict__ lng, const float* __restrict__ lnb,
        float* __restrict__ out) {
    extern __shared__ char sm[];
    __half* xs   = (__half*)sm;                       // [128][200] halves
    __half* hb   = (__half*)(sm + OFF_HB);            // [128][264] halves
    float* part   = (float*)(sm + OFF_PART);          // [128][8][2] (aliases dead bs)
    float* lnstat = (float*)(sm + OFF_LNSTAT);        // [128][2]
    __shared__ float s_gn[16][2];
    __shared__ float chA[256], chB[256];

    const int n = blockIdx.x, b = blockIdx.y;
    const int tid  = threadIdx.x;
    const int lane = tid & 31, warp = tid >> 5;
    const int g = lane >> 2, q = lane & 3;
    const int wm = warp & 1, wn = warp >> 1;          // 2 x 8 warp grid; tile 64t x 32c

    const __half* wbase = g_wh + (size_t)n * 512 * CIN;

    const uint32_t xs_u32 = (uint32_t)__cvta_generic_to_shared(xs);
    const uint32_t bs_u32 = xs_u32 + OFF_BS;

    const int a_row_off = (lane & 7) + ((lane >> 3) & 1) * 8;
    const int a_k_off   = ((lane >> 4) & 1) * 8;
    uint32_t addrA[4];
#pragma unroll
    for (int mi = 0; mi < 4; mi++)
        addrA[mi] = xs_u32 + (uint32_t)((wm * 64 + mi * 16 + a_row_off) * (XS_PITCH * 2) + a_k_off * 2);
    const int b_n_off = ((lane >> 4) & 1) * 8 + (lane & 7);
    const int b_k_off = ((lane >> 3) & 1) * 8;
    uint32_t addrB[2];
#pragma unroll
    for (int pp = 0; pp < 2; pp++)
        addrB[pp] = bs_u32 + (uint32_t)((wn * 32 + pp * 16 + b_n_off) * (BS_PITCH * 2) + b_k_off * 2);

    // stage one 64-k chunk of B (256 cols) into buffer `buf`; 4 cp.async per thread
    auto stage = [&](int p, int kc, int buf) {
        int col = tid >> 1, hv = tid & 1;
        const __half* src = wbase + (size_t)(p * 256 + col) * CIN + kc * 64 + hv * 32;
        uint32_t d = bs_u32 + (uint32_t)(buf * BS_STAGE + col * (BS_PITCH * 2) + hv * 64);
        cp_async16(d,      src);
        cp_async16(d + 16, src + 8);
        cp_async16(d + 32, src + 16);
        cp_async16(d + 48, src + 24);
        asm volatile("cp.async.commit_group;\n");
    };

    // ---- load x tile -> fp16 smem (overlap with first B stage) ----
    stage(0, 0, 0);
    for (int i = tid; i < 128 * 48; i += NT) {
        int t = i / 48, c4 = (i % 48) * 4;
        float4 v = *(const float4*)(x + ((size_t)(b * Tn + t) * Nn + n) * CIN + c4);
        __half2* dst = (__half2*)(xs + t * XS_PITCH + c4);
        dst[0] = __floats2half2_rn(v.x, v.y);
        dst[1] = __floats2half2_rn(v.z, v.w);
    }
    __syncthreads();

    float acc[4][4][4];
#pragma unroll
    for (int mi = 0; mi < 4; mi++)
#pragma unroll
        for (int ni = 0; ni < 4; ni++)
#pragma unroll
            for (int r = 0; r < 4; r++) acc[mi][ni][r] = 0.f;

    // ================= p0 mainloop: 3 chunks of 64-k =================
#pragma unroll 1
    for (int kc = 0; kc < 3; kc++) {
        if (kc < 2) {
            stage(0, kc + 1, (kc + 1) & 1);
            asm volatile("cp.async.wait_group 1;\n");
        } else {
            asm volatile("cp.async.wait_group 0;\n");
        }
        __syncthreads();
        const uint32_t bsel = (uint32_t)((kc & 1) * BS_STAGE);
#pragma unroll
        for (int ks = 0; ks < 4; ks++) {
            const uint32_t kbb = (uint32_t)((kc * 64 + ks * 16) * 2);
            uint32_t afr[4][4];
            uint32_t bfr[4][2];
#pragma unroll
            for (int mi = 0; mi < 4; mi++)
                ldsm_x4(afr[mi][0], afr[mi][1], afr[mi][2], afr[mi][3], addrA[mi] + kbb);
#pragma unroll
            for (int pp = 0; pp < 2; pp++)
                ldsm_x4(bfr[pp * 2][0], bfr[pp * 2][1], bfr[pp * 2 + 1][0], bfr[pp * 2 + 1][1],
                        addrB[pp] + bsel + (uint32_t)(ks * 32));
#pragma unroll
            for (int ni = 0; ni < 4; ni++)
#pragma unroll
                for (int mi = 0; mi < 4; mi++)
                    mma16816(acc[mi][ni], afr[mi], bfr[ni]);
        }
        __syncthreads();
    }

    // prefetch first p1 chunk; it streams during epilogue + conv
    stage(1, 0, 0);

    // ---- p0 epilogue: h -> fp16 hbuf[t][o] ----
#pragma unroll
    for (int mi = 0; mi < 4; mi++) {
#pragma unroll
        for (int half = 0; half < 2; half++) {
            int t = wm * 64 + mi * 16 + g + half * 8;
            int r = half * 2;
#pragma unroll
            for (int ni = 0; ni < 4; ni++) {
                int o0 = wn * 32 + ni * 8 + 2 * q;
                *(__half2*)(hb + t * HBUF_PITCH + o0) = __floats2half2_rn(acc[mi][ni][r], acc[mi][ni][r + 1]);
            }
        }
    }
    __syncthreads();

    // ---- temporal conv + GN stats; thread = (channel, t-half); static bounds ----
    const int o = tid & 255, hf = tid >> 8;
    const int ct0 = hf * 64, ct1 = ct0 + 64;
    const float w0 = convw[o * 3], w1 = convw[o * 3 + 1], w2 = convw[o * 3 + 2];
    float cprev = (ct0 == 0) ? 0.f : __half2float(hb[(ct0 - 1) * HBUF_PITCH + o]);
    float ccur  = __half2float(hb[ct0 * HBUF_PITCH + o]);
    float cbnd  = (ct1 == Tn) ? 0.f : __half2float(hb[ct1 * HBUF_PITCH + o]);
    __syncthreads();
    float cs = 0.f, cs2 = 0.f;
#pragma unroll 8
    for (int t = ct0; t < ct1; t++) {
        float nxt = (t == ct1 - 1) ? cbnd : __half2float(hb[(t + 1) * HBUF_PITCH + o]);
        float v = w0 * cprev + w1 * ccur + w2 * nxt;
        hb[t * HBUF_PITCH + o] = __float2half_rn(v);
        cs += v; cs2 += v * v;
        cprev = ccur; ccur = nxt;
    }
#pragma unroll
    for (int off = 16; off; off >>= 1) {
        cs  += __shfl_xor_sync(0xFFFFFFFFu, cs,  off);
        cs2 += __shfl_xor_sync(0xFFFFFFFFu, cs2, off);
    }
    if (lane == 0) { s_gn[warp][0] = cs; s_gn[warp][1] = cs2; }
    __syncthreads();
    if (hf == 0) {
        const int grp = warp & 7;
        float gs  = s_gn[grp][0] + s_gn[grp + 8][0];
        float gs2 = s_gn[grp][1] + s_gn[grp + 8][1];
        const float inv = 1.f / (32.f * Tn);
        float mu = gs * inv;
        float var = gs2 * inv - mu * mu;
        float rstd = rsqrtf(var + 1e-5f);
        float ga = gng[o] * rstd;
        chA[o] = ga;
        chB[o] = gnb[o] - mu * ga;
    }

    // zero acc for p1 (no sync needed before mainloop's own syncs)
#pragma unroll
    for (int mi = 0; mi < 4; mi++)
#pragma unroll
        for (int ni = 0; ni < 4; ni++)
#pragma unroll
            for (int r = 0; r < 4; r++) acc[mi][ni][r] = 0.f;

    // ================= p1 mainloop (res = x @ W_res): 3 chunks =================
#pragma unroll 1
    for (int kc = 0; kc < 3; kc++) {
        if (kc < 2) {
            stage(1, kc + 1, (kc + 1) & 1);
            asm volatile("cp.async.wait_group 1;\n");
        } else {
            asm volatile("cp.async.wait_group 0;\n");
        }
        __syncthreads();
        const uint32_t bsel = (uint32_t)((kc & 1) * BS_STAGE);
#pragma unroll
        for (int ks = 0; ks < 4; ks++) {
            const uint32_t kbb = (uint32_t)((kc * 64 + ks * 16) * 2);
            uint32_t afr[4][4];
            uint32_t bfr[4][2];
#pragma unroll
            for (int mi = 0; mi < 4; mi++)
                ldsm_x4(afr[mi][0], afr[mi][1], afr[mi][2], afr[mi][3], addrA[mi] + kbb);
#pragma unroll
            for (int pp = 0; pp < 2; pp++)
                ldsm_x4(bfr[pp * 2][0], bfr[pp * 2][1], bfr[pp * 2 + 1][0], bfr[pp * 2 + 1][1],
                        addrB[pp] + bsel + (uint32_t)(ks * 32));
#pragma unroll
            for (int ni = 0; ni < 4; ni++)
#pragma unroll
                for (int mi = 0; mi < 4; mi++)
                    mma16816(acc[mi][ni], afr[mi], bfr[ni]);
        }
        __syncthreads();
    }

    // ---- fold: v = h*ga + gb + res (in regs) + LN partial sums ----
#pragma unroll
    for (int mi = 0; mi < 4; mi++) {
#pragma unroll
        for (int half = 0; half < 2; half++) {
            int t = wm * 64 + mi * 16 + g + half * 8;
            int r = half * 2;
            float su = 0.f, sq = 0.f;
#pragma unroll
            for (int ni = 0; ni < 4; ni++) {
                int o0 = wn * 32 + ni * 8 + 2 * q;
                float2 hv = __half22float2(*(const __half2*)(hb + t * HBUF_PITCH + o0));
                float v0 = hv.x * chA[o0]     + chB[o0]     + acc[mi][ni][r];
                float v1 = hv.y * chA[o0 + 1] + chB[o0 + 1] + acc[mi][ni][r + 1];
                acc[mi][ni][r] = v0; acc[mi][ni][r + 1] = v1;
                su += v0 + v1; sq += v0 * v0 + v1 * v1;
            }
            su += __shfl_xor_sync(0xFFFFFFFFu, su, 1);
            su += __shfl_xor_sync(0xFFFFFFFFu, su, 2);
            sq += __shfl_xor_sync(0xFFFFFFFFu, sq, 1);
            sq += __shfl_xor_sync(0xFFFFFFFFu, sq, 2);
            if (q == 0) *(float2*)(part + (t * 8 + wn) * 2) = make_float2(su, sq);
        }
    }
    __syncthreads();
    if (tid < Tn) {
        float su = 0.f, sq = 0.f;
#pragma unroll
        for (int w = 0; w < 8; w++) {
            float2 p = *(const float2*)(part + (tid * 8 + w) * 2);
            su += p.x; sq += p.y;
        }
        float mu = su * (1.f / 256.f);
        float var = sq * (1.f / 256.f) - mu * mu;
        *(float2*)(lnstat + tid * 2) = make_float2(mu, rsqrtf(var + 1e-5f));
    }
    __syncthreads();

    // ---- apply LN + GELU, direct store ----
    float2 lg2[4], lb2[4];
#pragma unroll
    for (int ni = 0; ni < 4; ni++) {
        int o0 = wn * 32 + ni * 8 + 2 * q;
        lg2[ni] = *(const float2*)(lng + o0);
        lb2[ni] = *(const float2*)(lnb + o0);
    }
#pragma unroll
    for (int mi = 0; mi < 4; mi++) {
#pragma unroll
        for (int half = 0; half < 2; half++) {
            int t = wm * 64 + mi * 16 + g + half * 8;
            float2 st = *(const float2*)(lnstat + t * 2);
            float mu = st.x, rs = st.y;
            float* ob = out + ((size_t)(b * Tn + t) * Nn + n) * COUT;
            int r = half * 2;
#pragma unroll
            for (int ni = 0; ni < 4; ni++) {
                int o0 = wn * 32 + ni * 8 + 2 * q;
                float y0 = (acc[mi][ni][r]     - mu) * rs * lg2[ni].x + lb2[ni].x;
                float y1 = (acc[mi][ni][r + 1] - mu) * rs * lg2[ni].y + lb2[ni].y;
                *(float2*)(ob + o0) = make_float2(gelu_fast(y0), gelu_fast(y1));
            }
        }
    }
}

// ---------------- launch ----------------
extern "C" void kernel_launch(void* const* d_in, const int* in_sizes, int n_in,
                              void* d_out, int out_size) {
    const float* x     = (const float*)d_in[0];
    const float* A     = (const float*)d_in[1];
    const float* dw    = (const float*)d_in[2];
    const float* adj   = (const float*)d_in[3];
    const float* Wpw   = (const float*)d_in[4];
    const float* convw = (const float*)d_in[5];
    const float* gng   = (const float*)d_in[6];
    const float* gnb   = (const float*)d_in[7];
    const float* lng   = (const float*)d_in[8];
    const float* lnb   = (const float*)d_in[9];
    const float* Wres  = (const float*)d_in[10];
    float* out = (float*)d_out;

    cudaFuncSetAttribute(k_fused, cudaFuncAttributeMaxDynamicSharedMemorySize, SMEM_TOTAL);

    int total8 = Nn * 512 * 24;
    k_wh<<<(total8 + 255) / 256, 256>>>(A, adj, dw, Wpw, Wres);
    k_fused<<<dim3(Nn, Bsz), NT, SMEM_TOTAL>>>(x, convw, gng, gnb, lng, lnb, out);
}

// round 15
// speedup vs baseline: 3.1338x; 1.0248x over previous
#include <cuda_runtime.h>
#include <cuda_fp16.h>
#include <cstdint>
#include <math.h>

#define Bsz 32
#define Tn  128
#define Nn  47
#define CIN 192
#define COUT 256
#define KK  3

#define NT   512          // threads per block (16 warps)

#define XS_PITCH 200      // halves per t-row (192 + pad)
#define XS_BYTES (128 * XS_PITCH * 2)       // 51200
#define HBUF_PITCH 264    // halves per t-row (256 + pad)
#define HB_BYTES (128 * HBUF_PITCH * 2)     // 67584
#define OFF_HB   XS_BYTES                   // 51200
#define OFF_BS   (OFF_HB + HB_BYTES)        // 118784
#define BS_PITCH 72       // halves per col-row (64 k + 8 pad) = 144 B
#define BS_STAGE (256 * BS_PITCH * 2)       // 36864
#define SMEM_TOTAL (OFF_BS + 3 * BS_STAGE)  // 229376  (<= 232448 cap)

#define OFF_PART   OFF_BS                   // float[128][8][2] = 8192 B (bs dead by fold)
#define OFF_LNSTAT (OFF_BS + 8192)          // float[128][2]

// ---------------- scratch ----------------
__device__ __align__(256) __half g_wh[(size_t)Nn * 512 * CIN];  // [n][j][c]

// ---------------- K1: rowsum (in-block) + fused fp16 weights, 8-wide ----------------
__global__ void __launch_bounds__(256) k_wh(const float* __restrict__ A, const float* __restrict__ adj,
                                            const float* __restrict__ dw, const float* __restrict__ Wpw,
                                            const float* __restrict__ Wres) {
    __shared__ float srs[KK][2];
    const int idx8_0 = blockIdx.x * 256;
    const int n0 = idx8_0 / (24 * 512);
    const int warp = threadIdx.x >> 5, lane = threadIdx.x & 31;
    if (warp < 6) {
        int k = warp % KK, nn = n0 + warp / KK;
        if (nn < Nn) {
            const float* ar = A   + ((size_t)k * Nn + nn) * Nn;
            const float* rr = adj + ((size_t)k * Nn + nn) * Nn;
            float s = 0.f, sa = 0.f;
            for (int m = lane; m < Nn; m += 32) {
                float v = ar[m] + 0.3f * tanhf(rr[m]);
                s += v; sa += fabsf(v);
            }
#pragma unroll
            for (int o = 16; o; o >>= 1) {
                s  += __shfl_xor_sync(0xFFFFFFFFu, s,  o);
                sa += __shfl_xor_sync(0xFFFFFFFFu, sa, o);
            }
            if (lane == 0) srs[k][warp / KK] = s / fmaxf(sa, 1.0f);
        }
    }
    __syncthreads();

    const int idx8 = idx8_0 + threadIdx.x;
    if (idx8 >= Nn * 512 * 24) return;
    const int c0 = (idx8 % 24) * 8;
    const int j  = (idx8 / 24) & 511;
    const int n  = idx8 / (24 * 512);
    float w8[8];
    if (j < COUT) {
#pragma unroll
        for (int i = 0; i < 8; i++) w8[i] = 0.f;
#pragma unroll
        for (int k = 0; k < KK; k++) {
            float rs = srs[k][n - n0];
            const float* dwp = dw + k * CIN + c0;
            const float* wp  = Wpw + (size_t)j * (KK * CIN) + k * CIN + c0;
            float4 d0 = *(const float4*)dwp, d1 = *(const float4*)(dwp + 4);
            float4 p0 = *(const float4*)wp,  p1 = *(const float4*)(wp + 4);
            w8[0] += rs * d0.x * p0.x; w8[1] += rs * d0.y * p0.y;
            w8[2] += rs * d0.z * p0.z; w8[3] += rs * d0.w * p0.w;
            w8[4] += rs * d1.x * p1.x; w8[5] += rs * d1.y * p1.y;
            w8[6] += rs * d1.z * p1.z; w8[7] += rs * d1.w * p1.w;
        }
    } else {
        const float* rp = Wres + (size_t)(j - COUT) * CIN + c0;
        float4 r0 = *(const float4*)rp, r1 = *(const float4*)(rp + 4);
        w8[0] = r0.x; w8[1] = r0.y; w8[2] = r0.z; w8[3] = r0.w;
        w8[4] = r1.x; w8[5] = r1.y; w8[6] = r1.z; w8[7] = r1.w;
    }
    __half2 h2[4];
#pragma unroll
    for (int i = 0; i < 4; i++) h2[i] = __floats2half2_rn(w8[2 * i], w8[2 * i + 1]);
    *(uint4*)(g_wh + (size_t)idx8 * 8) = *(const uint4*)h2;
}

// ---------------- helpers ----------------
__device__ __forceinline__ void cp_async16(uint32_t dst, const void* src) {
    asm volatile("cp.async.cg.shared.global [%0], [%1], 16;\n" :: "r"(dst), "l"(src));
}
__device__ __forceinline__ void mma16816(float* d, const uint32_t* a, const uint32_t* b) {
    asm volatile(
        "mma.sync.aligned.m16n8k16.row.col.f32.f16.f16.f32 "
        "{%0,%1,%2,%3}, {%4,%5,%6,%7}, {%8,%9}, {%0,%1,%2,%3};\n"
        : "+f"(d[0]), "+f"(d[1]), "+f"(d[2]), "+f"(d[3])
        : "r"(a[0]), "r"(a[1]), "r"(a[2]), "r"(a[3]), "r"(b[0]), "r"(b[1]));
}
__device__ __forceinline__ void ldsm_x4(uint32_t& r0, uint32_t& r1, uint32_t& r2, uint32_t& r3,
                                        uint32_t addr) {
    asm volatile("ldmatrix.sync.aligned.m8n8.x4.shared.b16 {%0,%1,%2,%3}, [%4];"
                 : "=r"(r0), "=r"(r1), "=r"(r2), "=r"(r3) : "r"(addr));
}
// branch-free GELU: Abramowitz-Stegun 7.1.26 erf (|err| <= 1.5e-7)
__device__ __forceinline__ float gelu_fast(float v) {
    float x  = v * 0.70710678118654752f;
    float ax = fabsf(x);
    float t  = __fdividef(1.0f, fmaf(0.3275911f, ax, 1.0f));
    float p  = fmaf(fmaf(fmaf(fmaf(1.061405429f, t, -1.453152027f), t, 1.421413741f),
                         t, -0.284496736f), t, 0.254829592f);
    float e  = __expf(-ax * ax);
    float er = fmaf(-p * t, e, 1.0f);
    er = copysignf(er, x);
    return 0.5f * v * (1.0f + er);
}

// ---------------- K2: fused per-(b,n) block; 3-stage cp.async ring ----------------
__global__ void __launch_bounds__(NT, 1)
k_fused(const float* __restrict__ x, const float* __restrict__ convw,
        const float* __restrict__ gng, const float* __restrict__ gnb,
        const float* __restrict__ lng, const float* __restrict__ lnb,
        float* __restrict__ out) {
    extern __shared__ char sm[];
    __half* xs   = (__half*)sm;                       // [128][200] halves
    __half* hb   = (__half*)(sm + OFF_HB);            // [128][264] halves
    float* part   = (float*)(sm + OFF_PART);          // [128][8][2] (aliases dead bs)
    float* lnstat = (float*)(sm + OFF_LNSTAT);        // [128][2]
    __shared__ float s_gn[16][2];
    __shared__ float chA[256], chB[256];

    const int n = blockIdx.x, b = blockIdx.y;
    const int tid  = threadIdx.x;
    const int lane = tid & 31, warp = tid >> 5;
    const int g = lane >> 2, q = lane & 3;
    const int wm = warp & 1, wn = warp >> 1;          // 2 x 8 warp grid; tile 64t x 32c

    const __half* wbase = g_wh + (size_t)n * 512 * CIN;

    const uint32_t xs_u32 = (uint32_t)__cvta_generic_to_shared(xs);
    const uint32_t bs_u32 = xs_u32 + OFF_BS;

    const int a_row_off = (lane & 7) + ((lane >> 3) & 1) * 8;
    const int a_k_off   = ((lane >> 4) & 1) * 8;
    uint32_t addrA[4];
#pragma unroll
    for (int mi = 0; mi < 4; mi++)
        addrA[mi] = xs_u32 + (uint32_t)((wm * 64 + mi * 16 + a_row_off) * (XS_PITCH * 2) + a_k_off * 2);
    const int b_n_off = ((lane >> 4) & 1) * 8 + (lane & 7);
    const int b_k_off = ((lane >> 3) & 1) * 8;
    uint32_t addrB[2];
#pragma unroll
    for (int pp = 0; pp < 2; pp++)
        addrB[pp] = bs_u32 + (uint32_t)((wn * 32 + pp * 16 + b_n_off) * (BS_PITCH * 2) + b_k_off * 2);

    // stage chunk c (c in 0..5): p = c>=3, kcc = c%3 within pass, buf = c%3
    auto stage = [&](int c) {
        int p = (c >= 3) ? 1 : 0;
        int kcc = c - 3 * p;
        int col = tid >> 1, hv = tid & 1;
        const __half* src = wbase + (size_t)(p * 256 + col) * CIN + kcc * 64 + hv * 32;
        uint32_t d = bs_u32 + (uint32_t)((c % 3) * BS_STAGE + col * (BS_PITCH * 2) + hv * 64);
        cp_async16(d,      src);
        cp_async16(d + 16, src + 8);
        cp_async16(d + 32, src + 16);
        cp_async16(d + 48, src + 24);
        asm volatile("cp.async.commit_group;\n");
    };

    // one GEMM chunk-iteration: leading barrier only (3-buffer ring makes trailing barrier redundant)
    auto gemm_chunk = [&](int kc, float (*acc)[4][4]) {
        const uint32_t bsel = (uint32_t)((kc % 3) * BS_STAGE);
#pragma unroll
        for (int ks = 0; ks < 4; ks++) {
            const uint32_t kbb = (uint32_t)((kc * 64 + ks * 16) * 2);
            uint32_t afr[4][4];
            uint32_t bfr[4][2];
#pragma unroll
            for (int mi = 0; mi < 4; mi++)
                ldsm_x4(afr[mi][0], afr[mi][1], afr[mi][2], afr[mi][3], addrA[mi] + kbb);
#pragma unroll
            for (int pp = 0; pp < 2; pp++)
                ldsm_x4(bfr[pp * 2][0], bfr[pp * 2][1], bfr[pp * 2 + 1][0], bfr[pp * 2 + 1][1],
                        addrB[pp] + bsel + (uint32_t)(ks * 32));
#pragma unroll
            for (int ni = 0; ni < 4; ni++)
#pragma unroll
                for (int mi = 0; mi < 4; mi++)
                    mma16816(acc[mi][ni], afr[mi], bfr[ni]);
        }
    };

    // ---- prologue: deep prefetch + x load ----
    stage(0);
    stage(1);
    for (int i = tid; i < 128 * 48; i += NT) {
        int t = i / 48, c4 = (i % 48) * 4;
        float4 v = *(const float4*)(x + ((size_t)(b * Tn + t) * Nn + n) * CIN + c4);
        __half2* dst = (__half2*)(xs + t * XS_PITCH + c4);
        dst[0] = __floats2half2_rn(v.x, v.y);
        dst[1] = __floats2half2_rn(v.z, v.w);
    }
    __syncthreads();

    float acc[4][4][4];
#pragma unroll
    for (int mi = 0; mi < 4; mi++)
#pragma unroll
        for (int ni = 0; ni < 4; ni++)
#pragma unroll
            for (int r = 0; r < 4; r++) acc[mi][ni][r] = 0.f;

    // ================= p0 mainloop: chunks 0..2, leading-barrier only =================
#pragma unroll 1
    for (int kc = 0; kc < 3; kc++) {
        if (kc == 0) { stage(2); asm volatile("cp.async.wait_group 2;\n"); }
        else if (kc == 1) { asm volatile("cp.async.wait_group 1;\n"); }
        else { asm volatile("cp.async.wait_group 0;\n"); }
        __syncthreads();
        gemm_chunk(kc, acc);
    }

    // prefetch first p1 chunk (buf 0: last read at chunk 0, all warps past iter-2 barrier)
    stage(3);

    // ---- p0 epilogue: h -> fp16 hbuf[t][o] ----
#pragma unroll
    for (int mi = 0; mi < 4; mi++) {
#pragma unroll
        for (int half = 0; half < 2; half++) {
            int t = wm * 64 + mi * 16 + g + half * 8;
            int r = half * 2;
#pragma unroll
            for (int ni = 0; ni < 4; ni++) {
                int o0 = wn * 32 + ni * 8 + 2 * q;
                *(__half2*)(hb + t * HBUF_PITCH + o0) = __floats2half2_rn(acc[mi][ni][r], acc[mi][ni][r + 1]);
            }
        }
    }
    __syncthreads();

    // ---- temporal conv + GN stats; thread = (channel, t-half); static bounds ----
    const int o = tid & 255, hf = tid >> 8;
    const int ct0 = hf * 64, ct1 = ct0 + 64;
    const float w0 = convw[o * 3], w1 = convw[o * 3 + 1], w2 = convw[o * 3 + 2];
    float cprev = (ct0 == 0) ? 0.f : __half2float(hb[(ct0 - 1) * HBUF_PITCH + o]);
    float ccur  = __half2float(hb[ct0 * HBUF_PITCH + o]);
    float cbnd  = (ct1 == Tn) ? 0.f : __half2float(hb[ct1 * HBUF_PITCH + o]);
    __syncthreads();
    float cs = 0.f, cs2 = 0.f;
#pragma unroll 8
    for (int t = ct0; t < ct1; t++) {
        float nxt = (t == ct1 - 1) ? cbnd : __half2float(hb[(t + 1) * HBUF_PITCH + o]);
        float v = w0 * cprev + w1 * ccur + w2 * nxt;
        hb[t * HBUF_PITCH + o] = __float2half_rn(v);
        cs += v; cs2 += v * v;
        cprev = ccur; ccur = nxt;
    }
#pragma unroll
    for (int off = 16; off; off >>= 1) {
        cs  += __shfl_xor_sync(0xFFFFFFFFu, cs,  off);
        cs2 += __shfl_xor_sync(0xFFFFFFFFu, cs2, off);
    }
    if (lane == 0) { s_gn[warp][0] = cs; s_gn[warp][1] = cs2; }
    __syncthreads();
    if (hf == 0) {
        const int grp = warp & 7;
        float gs  = s_gn[grp][0] + s_gn[grp + 8][0];
        float gs2 = s_gn[grp][1] + s_gn[grp + 8][1];
        const float inv = 1.f / (32.f * Tn);
        float mu = gs * inv;
        float var = gs2 * inv - mu * mu;
        float rstd = rsqrtf(var + 1e-5f);
        float ga = gng[o] * rstd;
        chA[o] = ga;
        chB[o] = gnb[o] - mu * ga;
    }

    // prefetch second p1 chunk during phase transition (buf 1: last read chunk 1)
    stage(4);

    // zero acc for p1
#pragma unroll
    for (int mi = 0; mi < 4; mi++)
#pragma unroll
        for (int ni = 0; ni < 4; ni++)
#pragma unroll
            for (int r = 0; r < 4; r++) acc[mi][ni][r] = 0.f;

    // ================= p1 mainloop: chunks 3..5 =================
#pragma unroll 1
    for (int kc = 0; kc < 3; kc++) {
        if (kc == 0) { stage(5); asm volatile("cp.async.wait_group 2;\n"); }
        else if (kc == 1) { asm volatile("cp.async.wait_group 1;\n"); }
        else { asm volatile("cp.async.wait_group 0;\n"); }
        __syncthreads();
        gemm_chunk(kc, acc);
    }
    __syncthreads();   // bs region about to be reused as part/lnstat

    // ---- fold: v = h*ga + gb + res (in regs) + LN partial sums ----
#pragma unroll
    for (int mi = 0; mi < 4; mi++) {
#pragma unroll
        for (int half = 0; half < 2; half++) {
            int t = wm * 64 + mi * 16 + g + half * 8;
            int r = half * 2;
            float su = 0.f, sq = 0.f;
#pragma unroll
            for (int ni = 0; ni < 4; ni++) {
                int o0 = wn * 32 + ni * 8 + 2 * q;
                float2 hv = __half22float2(*(const __half2*)(hb + t * HBUF_PITCH + o0));
                float v0 = hv.x * chA[o0]     + chB[o0]     + acc[mi][ni][r];
                float v1 = hv.y * chA[o0 + 1] + chB[o0 + 1] + acc[mi][ni][r + 1];
                acc[mi][ni][r] = v0; acc[mi][ni][r + 1] = v1;
                su += v0 + v1; sq += v0 * v0 + v1 * v1;
            }
            su += __shfl_xor_sync(0xFFFFFFFFu, su, 1);
            su += __shfl_xor_sync(0xFFFFFFFFu, su, 2);
            sq += __shfl_xor_sync(0xFFFFFFFFu, sq, 1);
            sq += __shfl_xor_sync(0xFFFFFFFFu, sq, 2);
            if (q == 0) *(float2*)(part + (t * 8 + wn) * 2) = make_float2(su, sq);
        }
    }
    __syncthreads();
    if (tid < Tn) {
        float su = 0.f, sq = 0.f;
#pragma unroll
        for (int w = 0; w < 8; w++) {
            float2 p = *(const float2*)(part + (tid * 8 + w) * 2);
            su += p.x; sq += p.y;
        }
        float mu = su * (1.f / 256.f);
        float var = sq * (1.f / 256.f) - mu * mu;
        *(float2*)(lnstat + tid * 2) = make_float2(mu, rsqrtf(var + 1e-5f));
    }
    __syncthreads();

    // ---- apply LN + GELU, direct store ----
    float2 lg2[4], lb2[4];
#pragma unroll
    for (int ni = 0; ni < 4; ni++) {
        int o0 = wn * 32 + ni * 8 + 2 * q;
        lg2[ni] = *(const float2*)(lng + o0);
        lb2[ni] = *(const float2*)(lnb + o0);
    }
#pragma unroll
    for (int mi = 0; mi < 4; mi++) {
#pragma unroll
        for (int half = 0; half < 2; half++) {
            int t = wm * 64 + mi * 16 + g + half * 8;
            float2 st = *(const float2*)(lnstat + t * 2);
            float mu = st.x, rs = st.y;
            float* ob = out + ((size_t)(b * Tn + t) * Nn + n) * COUT;
            int r = half * 2;
#pragma unroll
            for (int ni = 0; ni < 4; ni++) {
                int o0 = wn * 32 + ni * 8 + 2 * q;
                float y0 = (acc[mi][ni][r]     - mu) * rs * lg2[ni].x + lb2[ni].x;
                float y1 = (acc[mi][ni][r + 1] - mu) * rs * lg2[ni].y + lb2[ni].y;
                *(float2*)(ob + o0) = make_float2(gelu_fast(y0), gelu_fast(y1));
            }
        }
    }
}

// ---------------- launch ----------------
extern "C" void kernel_launch(void* const* d_in, const int* in_sizes, int n_in,
                              void* d_out, int out_size) {
    const float* x     = (const float*)d_in[0];
    const float* A     = (const float*)d_in[1];
    const float* dw    = (const float*)d_in[2];
    const float* adj   = (const float*)d_in[3];
    const float* Wpw   = (const float*)d_in[4];
    const float* convw = (const float*)d_in[5];
    const float* gng   = (const float*)d_in[6];
    const float* gnb   = (const float*)d_in[7];
    const float* lng   = (const float*)d_in[8];
    const float* lnb   = (const float*)d_in[9];
    const float* Wres  = (const float*)d_in[10];
    float* out = (float*)d_out;

    cudaFuncSetAttribute(k_fused, cudaFuncAttributeMaxDynamicSharedMemorySize, SMEM_TOTAL);

    int total8 = Nn * 512 * 24;
    k_wh<<<(total8 + 255) / 256, 256>>>(A, adj, dw, Wpw, Wres);
    k_fused<<<dim3(Nn, Bsz), NT, SMEM_TOTAL>>>(x, convw, gng, gnb, lng, lnb, out);
}

// round 16
// speedup vs baseline: 3.6251x; 1.1568x over previous
#include <cuda_runtime.h>
#include <cuda_fp16.h>
#include <cstdint>
#include <math.h>

#define Bsz 32
#define Tn  128
#define Nn  47
#define CIN 192
#define COUT 256
#define KK  3

#define NT   1024         // threads per block (32 warps)

#define XS_PITCH 200      // halves per t-row (192 + pad)
#define XS_BYTES (128 * XS_PITCH * 2)       // 51200
#define HBUF_PITCH 264    // halves per t-row (256 + pad)
#define HB_BYTES (128 * HBUF_PITCH * 2)     // 67584
#define OFF_HB   XS_BYTES                   // 51200
#define OFF_BS   (OFF_HB + HB_BYTES)        // 118784
#define BS_PITCH 72       // halves per col-row (64 k + 8 pad) = 144 B
#define BS_STAGE (256 * BS_PITCH * 2)       // 36864
#define SMEM_TOTAL (OFF_BS + 3 * BS_STAGE)  // 229376

#define OFF_PART   OFF_BS                   // float[128][8][2] = 8192 B (bs dead by fold)
#define OFF_LNSTAT (OFF_BS + 8192)          // float[128][2]

// ---------------- scratch ----------------
__device__ __align__(256) __half g_wh[(size_t)Nn * 512 * CIN];  // [n][j][c]

// ---------------- K1: rowsum (in-block) + fused fp16 weights, 8-wide ----------------
__global__ void __launch_bounds__(256) k_wh(const float* __restrict__ A, const float* __restrict__ adj,
                                            const float* __restrict__ dw, const float* __restrict__ Wpw,
                                            const float* __restrict__ Wres) {
    __shared__ float srs[KK][2];
    const int idx8_0 = blockIdx.x * 256;
    const int n0 = idx8_0 / (24 * 512);
    const int warp = threadIdx.x >> 5, lane = threadIdx.x & 31;
    if (warp < 6) {
        int k = warp % KK, nn = n0 + warp / KK;
        if (nn < Nn) {
            const float* ar = A   + ((size_t)k * Nn + nn) * Nn;
            const float* rr = adj + ((size_t)k * Nn + nn) * Nn;
            float s = 0.f, sa = 0.f;
            for (int m = lane; m < Nn; m += 32) {
                float v = ar[m] + 0.3f * tanhf(rr[m]);
                s += v; sa += fabsf(v);
            }
#pragma unroll
            for (int o = 16; o; o >>= 1) {
                s  += __shfl_xor_sync(0xFFFFFFFFu, s,  o);
                sa += __shfl_xor_sync(0xFFFFFFFFu, sa, o);
            }
            if (lane == 0) srs[k][warp / KK] = s / fmaxf(sa, 1.0f);
        }
    }
    __syncthreads();

    const int idx8 = idx8_0 + threadIdx.x;
    if (idx8 >= Nn * 512 * 24) return;
    const int c0 = (idx8 % 24) * 8;
    const int j  = (idx8 / 24) & 511;
    const int n  = idx8 / (24 * 512);
    float w8[8];
    if (j < COUT) {
#pragma unroll
        for (int i = 0; i < 8; i++) w8[i] = 0.f;
#pragma unroll
        for (int k = 0; k < KK; k++) {
            float rs = srs[k][n - n0];
            const float* dwp = dw + k * CIN + c0;
            const float* wp  = Wpw + (size_t)j * (KK * CIN) + k * CIN + c0;
            float4 d0 = *(const float4*)dwp, d1 = *(const float4*)(dwp + 4);
            float4 p0 = *(const float4*)wp,  p1 = *(const float4*)(wp + 4);
            w8[0] += rs * d0.x * p0.x; w8[1] += rs * d0.y * p0.y;
            w8[2] += rs * d0.z * p0.z; w8[3] += rs * d0.w * p0.w;
            w8[4] += rs * d1.x * p1.x; w8[5] += rs * d1.y * p1.y;
            w8[6] += rs * d1.z * p1.z; w8[7] += rs * d1.w * p1.w;
        }
    } else {
        const float* rp = Wres + (size_t)(j - COUT) * CIN + c0;
        float4 r0 = *(const float4*)rp, r1 = *(const float4*)(rp + 4);
        w8[0] = r0.x; w8[1] = r0.y; w8[2] = r0.z; w8[3] = r0.w;
        w8[4] = r1.x; w8[5] = r1.y; w8[6] = r1.z; w8[7] = r1.w;
    }
    __half2 h2[4];
#pragma unroll
    for (int i = 0; i < 4; i++) h2[i] = __floats2half2_rn(w8[2 * i], w8[2 * i + 1]);
    *(uint4*)(g_wh + (size_t)idx8 * 8) = *(const uint4*)h2;
}

// ---------------- helpers ----------------
__device__ __forceinline__ void cp_async16(uint32_t dst, const void* src) {
    asm volatile("cp.async.cg.shared.global [%0], [%1], 16;\n" :: "r"(dst), "l"(src));
}
__device__ __forceinline__ void mma16816(float* d, const uint32_t* a, const uint32_t* b) {
    asm volatile(
        "mma.sync.aligned.m16n8k16.row.col.f32.f16.f16.f32 "
        "{%0,%1,%2,%3}, {%4,%5,%6,%7}, {%8,%9}, {%0,%1,%2,%3};\n"
        : "+f"(d[0]), "+f"(d[1]), "+f"(d[2]), "+f"(d[3])
        : "r"(a[0]), "r"(a[1]), "r"(a[2]), "r"(a[3]), "r"(b[0]), "r"(b[1]));
}
__device__ __forceinline__ void ldsm_x4(uint32_t& r0, uint32_t& r1, uint32_t& r2, uint32_t& r3,
                                        uint32_t addr) {
    asm volatile("ldmatrix.sync.aligned.m8n8.x4.shared.b16 {%0,%1,%2,%3}, [%4];"
                 : "=r"(r0), "=r"(r1), "=r"(r2), "=r"(r3) : "r"(addr));
}
// branch-free GELU: Abramowitz-Stegun 7.1.26 erf (|err| <= 1.5e-7)
__device__ __forceinline__ float gelu_fast(float v) {
    float x  = v * 0.70710678118654752f;
    float ax = fabsf(x);
    float t  = __fdividef(1.0f, fmaf(0.3275911f, ax, 1.0f));
    float p  = fmaf(fmaf(fmaf(fmaf(1.061405429f, t, -1.453152027f), t, 1.421413741f),
                         t, -0.284496736f), t, 0.254829592f);
    float e  = __expf(-ax * ax);
    float er = fmaf(-p * t, e, 1.0f);
    er = copysignf(er, x);
    return 0.5f * v * (1.0f + er);
}

// ---------------- K2: fused per-(b,n) block; 32 warps; 3-stage ring ----------------
__global__ void __launch_bounds__(NT, 1)
k_fused(const float* __restrict__ x, const float* __restrict__ convw,
        const float* __restrict__ gng, const float* __restrict__ gnb,
        const float* __restrict__ lng, const float* __restrict__ lnb,
        float* __restrict__ out) {
    extern __shared__ char sm[];
    __half* xs   = (__half*)sm;                       // [128][200] halves
    __half* hb   = (__half*)(sm + OFF_HB);            // [128][264] halves
    float* part   = (float*)(sm + OFF_PART);          // [128][8][2] (aliases dead bs)
    float* lnstat = (float*)(sm + OFF_LNSTAT);        // [128][2]
    __shared__ float s_gn[32][2];
    __shared__ float chA[256], chB[256];

    const int n = blockIdx.x, b = blockIdx.y;
    const int tid  = threadIdx.x;
    const int lane = tid & 31, warp = tid >> 5;
    const int g = lane >> 2, q = lane & 3;
    const int wm = warp & 3, wn = warp >> 2;          // 4 x 8 warp grid; tile 32t x 32c

    const __half* wbase = g_wh + (size_t)n * 512 * CIN;

    const uint32_t xs_u32 = (uint32_t)__cvta_generic_to_shared(xs);
    const uint32_t bs_u32 = xs_u32 + OFF_BS;

    const int a_row_off = (lane & 7) + ((lane >> 3) & 1) * 8;
    const int a_k_off   = ((lane >> 4) & 1) * 8;
    uint32_t addrA[2];
#pragma unroll
    for (int mi = 0; mi < 2; mi++)
        addrA[mi] = xs_u32 + (uint32_t)((wm * 32 + mi * 16 + a_row_off) * (XS_PITCH * 2) + a_k_off * 2);
    const int b_n_off = ((lane >> 4) & 1) * 8 + (lane & 7);
    const int b_k_off = ((lane >> 3) & 1) * 8;
    uint32_t addrB[2];
#pragma unroll
    for (int pp = 0; pp < 2; pp++)
        addrB[pp] = bs_u32 + (uint32_t)((wn * 32 + pp * 16 + b_n_off) * (BS_PITCH * 2) + b_k_off * 2);

    // stage chunk c (0..5): p = c>=3, kcc = c%3, buf = c%3; 2 cp.async per thread
    auto stage = [&](int c) {
        int p = (c >= 3) ? 1 : 0;
        int kcc = c - 3 * p;
        int col = tid >> 2, hv = tid & 3;
        const __half* src = wbase + (size_t)(p * 256 + col) * CIN + kcc * 64 + hv * 16;
        uint32_t d = bs_u32 + (uint32_t)((c % 3) * BS_STAGE + col * (BS_PITCH * 2) + hv * 32);
        cp_async16(d,      src);
        cp_async16(d + 16, src + 8);
        asm volatile("cp.async.commit_group;\n");
    };

    // one GEMM chunk-iteration (leading barrier handled by caller); pp-split to cap live regs
    auto gemm_chunk = [&](int kc, float (*acc)[4][4]) {
        const uint32_t bsel = (uint32_t)((kc % 3) * BS_STAGE);
#pragma unroll
        for (int ks = 0; ks < 4; ks++) {
            const uint32_t kbb = (uint32_t)((kc * 64 + ks * 16) * 2);
            uint32_t afr[2][4];
#pragma unroll
            for (int mi = 0; mi < 2; mi++)
                ldsm_x4(afr[mi][0], afr[mi][1], afr[mi][2], afr[mi][3], addrA[mi] + kbb);
#pragma unroll
            for (int pp = 0; pp < 2; pp++) {
                uint32_t bfr[2][2];
                ldsm_x4(bfr[0][0], bfr[0][1], bfr[1][0], bfr[1][1],
                        addrB[pp] + bsel + (uint32_t)(ks * 32));
#pragma unroll
                for (int nj = 0; nj < 2; nj++)
#pragma unroll
                    for (int mi = 0; mi < 2; mi++)
                        mma16816(acc[mi][pp * 2 + nj], afr[mi], bfr[nj]);
            }
        }
    };

    // ---- prologue: deep prefetch + x load ----
    stage(0);
    stage(1);
    for (int i = tid; i < 128 * 48; i += NT) {
        int t = i / 48, c4 = (i % 48) * 4;
        float4 v = *(const float4*)(x + ((size_t)(b * Tn + t) * Nn + n) * CIN + c4);
        __half2* dst = (__half2*)(xs + t * XS_PITCH + c4);
        dst[0] = __floats2half2_rn(v.x, v.y);
        dst[1] = __floats2half2_rn(v.z, v.w);
    }
    __syncthreads();

    float acc[2][4][4];
#pragma unroll
    for (int mi = 0; mi < 2; mi++)
#pragma unroll
        for (int ni = 0; ni < 4; ni++)
#pragma unroll
            for (int r = 0; r < 4; r++) acc[mi][ni][r] = 0.f;

    // ================= p0 mainloop: chunks 0..2, leading-barrier only =================
#pragma unroll 1
    for (int kc = 0; kc < 3; kc++) {
        if (kc == 0) { stage(2); asm volatile("cp.async.wait_group 2;\n"); }
        else if (kc == 1) { asm volatile("cp.async.wait_group 1;\n"); }
        else { asm volatile("cp.async.wait_group 0;\n"); }
        __syncthreads();
        gemm_chunk(kc, acc);
    }

    // prefetch first p1 chunk (buf 0 free: all warps past iter-2 barrier)
    stage(3);

    // ---- p0 epilogue: h -> fp16 hbuf[t][o] ----
#pragma unroll
    for (int mi = 0; mi < 2; mi++) {
#pragma unroll
        for (int half = 0; half < 2; half++) {
            int t = wm * 32 + mi * 16 + g + half * 8;
            int r = half * 2;
#pragma unroll
            for (int ni = 0; ni < 4; ni++) {
                int o0 = wn * 32 + ni * 8 + 2 * q;
                *(__half2*)(hb + t * HBUF_PITCH + o0) = __floats2half2_rn(acc[mi][ni][r], acc[mi][ni][r + 1]);
            }
        }
    }
    __syncthreads();

    // ---- temporal conv + GN stats; thread = (channel, t-quarter) ----
    const int o = tid & 255, qf = tid >> 8;           // qf in 0..3
    const int ct0 = qf * 32, ct1 = ct0 + 32;
    const float w0 = convw[o * 3], w1 = convw[o * 3 + 1], w2 = convw[o * 3 + 2];
    float cprev = (ct0 == 0) ? 0.f : __half2float(hb[(ct0 - 1) * HBUF_PITCH + o]);
    float ccur  = __half2float(hb[ct0 * HBUF_PITCH + o]);
    float cbnd  = (ct1 == Tn) ? 0.f : __half2float(hb[ct1 * HBUF_PITCH + o]);
    __syncthreads();
    float cs = 0.f, cs2 = 0.f;
#pragma unroll 8
    for (int t = ct0; t < ct1; t++) {
        float nxt = (t == ct1 - 1) ? cbnd : __half2float(hb[(t + 1) * HBUF_PITCH + o]);
        float v = w0 * cprev + w1 * ccur + w2 * nxt;
        hb[t * HBUF_PITCH + o] = __float2half_rn(v);
        cs += v; cs2 += v * v;
        cprev = ccur; ccur = nxt;
    }
#pragma unroll
    for (int off = 16; off; off >>= 1) {
        cs  += __shfl_xor_sync(0xFFFFFFFFu, cs,  off);
        cs2 += __shfl_xor_sync(0xFFFFFFFFu, cs2, off);
    }
    if (lane == 0) { s_gn[warp][0] = cs; s_gn[warp][1] = cs2; }
    __syncthreads();
    if (qf == 0) {
        const int grp = warp & 7;
        float gs  = s_gn[grp][0]      + s_gn[grp + 8][0]
                  + s_gn[grp + 16][0] + s_gn[grp + 24][0];
        float gs2 = s_gn[grp][1]      + s_gn[grp + 8][1]
                  + s_gn[grp + 16][1] + s_gn[grp + 24][1];
        const float inv = 1.f / (32.f * Tn);
        float mu = gs * inv;
        float var = gs2 * inv - mu * mu;
        float rstd = rsqrtf(var + 1e-5f);
        float ga = gng[o] * rstd;
        chA[o] = ga;
        chB[o] = gnb[o] - mu * ga;
    }

    // prefetch second p1 chunk during phase transition (buf 1 free)
    stage(4);

    // zero acc for p1
#pragma unroll
    for (int mi = 0; mi < 2; mi++)
#pragma unroll
        for (int ni = 0; ni < 4; ni++)
#pragma unroll
            for (int r = 0; r < 4; r++) acc[mi][ni][r] = 0.f;

    // ================= p1 mainloop: chunks 3..5 =================
#pragma unroll 1
    for (int kc = 0; kc < 3; kc++) {
        if (kc == 0) { stage(5); asm volatile("cp.async.wait_group 2;\n"); }
        else if (kc == 1) { asm volatile("cp.async.wait_group 1;\n"); }
        else { asm volatile("cp.async.wait_group 0;\n"); }
        __syncthreads();
        gemm_chunk(kc, acc);
    }
    __syncthreads();   // bs region about to be reused as part/lnstat

    // ---- fold: v = h*ga + gb + res (in regs) + LN partial sums ----
#pragma unroll
    for (int mi = 0; mi < 2; mi++) {
#pragma unroll
        for (int half = 0; half < 2; half++) {
            int t = wm * 32 + mi * 16 + g + half * 8;
            int r = half * 2;
            float su = 0.f, sq = 0.f;
#pragma unroll
            for (int ni = 0; ni < 4; ni++) {
                int o0 = wn * 32 + ni * 8 + 2 * q;
                float2 hv = __half22float2(*(const __half2*)(hb + t * HBUF_PITCH + o0));
                float v0 = hv.x * chA[o0]     + chB[o0]     + acc[mi][ni][r];
                float v1 = hv.y * chA[o0 + 1] + chB[o0 + 1] + acc[mi][ni][r + 1];
                acc[mi][ni][r] = v0; acc[mi][ni][r + 1] = v1;
                su += v0 + v1; sq += v0 * v0 + v1 * v1;
            }
            su += __shfl_xor_sync(0xFFFFFFFFu, su, 1);
            su += __shfl_xor_sync(0xFFFFFFFFu, su, 2);
            sq += __shfl_xor_sync(0xFFFFFFFFu, sq, 1);
            sq += __shfl_xor_sync(0xFFFFFFFFu, sq, 2);
            if (q == 0) *(float2*)(part + (t * 8 + wn) * 2) = make_float2(su, sq);
        }
    }
    __syncthreads();
    if (tid < Tn) {
        float su = 0.f, sq = 0.f;
#pragma unroll
        for (int w = 0; w < 8; w++) {
            float2 p = *(const float2*)(part + (tid * 8 + w) * 2);
            su += p.x; sq += p.y;
        }
        float mu = su * (1.f / 256.f);
        float var = sq * (1.f / 256.f) - mu * mu;
        *(float2*)(lnstat + tid * 2) = make_float2(mu, rsqrtf(var + 1e-5f));
    }
    __syncthreads();

    // ---- apply LN + GELU, direct store ----
#pragma unroll
    for (int mi = 0; mi < 2; mi++) {
#pragma unroll
        for (int half = 0; half < 2; half++) {
            int t = wm * 32 + mi * 16 + g + half * 8;
            float2 st = *(const float2*)(lnstat + t * 2);
            float mu = st.x, rs = st.y;
            float* ob = out + ((size_t)(b * Tn + t) * Nn + n) * COUT;
            int r = half * 2;
#pragma unroll
            for (int ni = 0; ni < 4; ni++) {
                int o0 = wn * 32 + ni * 8 + 2 * q;
                float2 lg = *(const float2*)(lng + o0);
                float2 lb = *(const float2*)(lnb + o0);
                float y0 = (acc[mi][ni][r]     - mu) * rs * lg.x + lb.x;
                float y1 = (acc[mi][ni][r + 1] - mu) * rs * lg.y + lb.y;
                *(float2*)(ob + o0) = make_float2(gelu_fast(y0), gelu_fast(y1));
            }
        }
    }
}

// ---------------- launch ----------------
extern "C" void kernel_launch(void* const* d_in, const int* in_sizes, int n_in,
                              void* d_out, int out_size) {
    const float* x     = (const float*)d_in[0];
    const float* A     = (const float*)d_in[1];
    const float* dw    = (const float*)d_in[2];
    const float* adj   = (const float*)d_in[3];
    const float* Wpw   = (const float*)d_in[4];
    const float* convw = (const float*)d_in[5];
    const float* gng   = (const float*)d_in[6];
    const float* gnb   = (const float*)d_in[7];
    const float* lng   = (const float*)d_in[8];
    const float* lnb   = (const float*)d_in[9];
    const float* Wres  = (const float*)d_in[10];
    float* out = (float*)d_out;

    cudaFuncSetAttribute(k_fused, cudaFuncAttributeMaxDynamicSharedMemorySize, SMEM_TOTAL);

    int total8 = Nn * 512 * 24;
    k_wh<<<(total8 + 255) / 256, 256>>>(A, adj, dw, Wpw, Wres);
    k_fused<<<dim3(Nn, Bsz), NT, SMEM_TOTAL>>>(x, convw, gng, gnb, lng, lnb, out);
}

// round 17
// speedup vs baseline: 3.6912x; 1.0182x over previous
#include <cuda_runtime.h>
#include <cuda_fp16.h>
#include <cstdint>
#include <math.h>

#define Bsz 32
#define Tn  128
#define Nn  47
#define CIN 192
#define COUT 256
#define KK  3

#define NT   1024         // threads per block (32 warps)

#define XS_PITCH 200      // halves per t-row (192 + pad)
#define XS_BYTES (128 * XS_PITCH * 2)       // 51200
#define HBUF_PITCH 264    // halves per t-row (256 + pad)
#define HB_BYTES (128 * HBUF_PITCH * 2)     // 67584
#define OFF_HB   XS_BYTES                   // 51200
#define OFF_BS   (OFF_HB + HB_BYTES)        // 118784
#define BS_PITCH 72       // halves per col-row (64 k + 8 pad) = 144 B
#define BS_STAGE (256 * BS_PITCH * 2)       // 36864
#define SMEM_TOTAL (OFF_BS + 3 * BS_STAGE)  // 229376

#define OFF_PART   OFF_BS                   // float[128][8][2] = 8192 B (bs dead by fold)
#define OFF_LNSTAT (OFF_BS + 8192)          // float[128][2]

// ---------------- scratch ----------------
__device__ __align__(256) __half g_wh[(size_t)Nn * 512 * CIN];  // [n][j][c]

// ---------------- K1: rowsum (in-block) + fused fp16 weights, 8-wide ----------------
__global__ void __launch_bounds__(256) k_wh(const float* __restrict__ A, const float* __restrict__ adj,
                                            const float* __restrict__ dw, const float* __restrict__ Wpw,
                                            const float* __restrict__ Wres) {
    __shared__ float srs[KK][2];
    const int idx8_0 = blockIdx.x * 256;
    const int n0 = idx8_0 / (24 * 512);
    const int warp = threadIdx.x >> 5, lane = threadIdx.x & 31;
    if (warp < 6) {
        int k = warp % KK, nn = n0 + warp / KK;
        if (nn < Nn) {
            const float* ar = A   + ((size_t)k * Nn + nn) * Nn;
            const float* rr = adj + ((size_t)k * Nn + nn) * Nn;
            float s = 0.f, sa = 0.f;
            for (int m = lane; m < Nn; m += 32) {
                float v = ar[m] + 0.3f * tanhf(rr[m]);
                s += v; sa += fabsf(v);
            }
#pragma unroll
            for (int o = 16; o; o >>= 1) {
                s  += __shfl_xor_sync(0xFFFFFFFFu, s,  o);
                sa += __shfl_xor_sync(0xFFFFFFFFu, sa, o);
            }
            if (lane == 0) srs[k][warp / KK] = s / fmaxf(sa, 1.0f);
        }
    }
    __syncthreads();

    const int idx8 = idx8_0 + threadIdx.x;
    if (idx8 >= Nn * 512 * 24) return;
    const int c0 = (idx8 % 24) * 8;
    const int j  = (idx8 / 24) & 511;
    const int n  = idx8 / (24 * 512);
    float w8[8];
    if (j < COUT) {
#pragma unroll
        for (int i = 0; i < 8; i++) w8[i] = 0.f;
#pragma unroll
        for (int k = 0; k < KK; k++) {
            float rs = srs[k][n - n0];
            const float* dwp = dw + k * CIN + c0;
            const float* wp  = Wpw + (size_t)j * (KK * CIN) + k * CIN + c0;
            float4 d0 = *(const float4*)dwp, d1 = *(const float4*)(dwp + 4);
            float4 p0 = *(const float4*)wp,  p1 = *(const float4*)(wp + 4);
            w8[0] += rs * d0.x * p0.x; w8[1] += rs * d0.y * p0.y;
            w8[2] += rs * d0.z * p0.z; w8[3] += rs * d0.w * p0.w;
            w8[4] += rs * d1.x * p1.x; w8[5] += rs * d1.y * p1.y;
            w8[6] += rs * d1.z * p1.z; w8[7] += rs * d1.w * p1.w;
        }
    } else {
        const float* rp = Wres + (size_t)(j - COUT) * CIN + c0;
        float4 r0 = *(const float4*)rp, r1 = *(const float4*)(rp + 4);
        w8[0] = r0.x; w8[1] = r0.y; w8[2] = r0.z; w8[3] = r0.w;
        w8[4] = r1.x; w8[5] = r1.y; w8[6] = r1.z; w8[7] = r1.w;
    }
    __half2 h2[4];
#pragma unroll
    for (int i = 0; i < 4; i++) h2[i] = __floats2half2_rn(w8[2 * i], w8[2 * i + 1]);
    *(uint4*)(g_wh + (size_t)idx8 * 8) = *(const uint4*)h2;
}

// ---------------- helpers ----------------
__device__ __forceinline__ void cp_async16(uint32_t dst, const void* src) {
    asm volatile("cp.async.cg.shared.global [%0], [%1], 16;\n" :: "r"(dst), "l"(src));
}
__device__ __forceinline__ void mma16816(float* d, const uint32_t* a, const uint32_t* b) {
    asm volatile(
        "mma.sync.aligned.m16n8k16.row.col.f32.f16.f16.f32 "
        "{%0,%1,%2,%3}, {%4,%5,%6,%7}, {%8,%9}, {%0,%1,%2,%3};\n"
        : "+f"(d[0]), "+f"(d[1]), "+f"(d[2]), "+f"(d[3])
        : "r"(a[0]), "r"(a[1]), "r"(a[2]), "r"(a[3]), "r"(b[0]), "r"(b[1]));
}
__device__ __forceinline__ void ldsm_x4(uint32_t& r0, uint32_t& r1, uint32_t& r2, uint32_t& r3,
                                        uint32_t addr) {
    asm volatile("ldmatrix.sync.aligned.m8n8.x4.shared.b16 {%0,%1,%2,%3}, [%4];"
                 : "=r"(r0), "=r"(r1), "=r"(r2), "=r"(r3) : "r"(addr));
}
// branch-free GELU: Abramowitz-Stegun 7.1.26 erf (|err| <= 1.5e-7)
__device__ __forceinline__ float gelu_fast(float v) {
    float x  = v * 0.70710678118654752f;
    float ax = fabsf(x);
    float t  = __fdividef(1.0f, fmaf(0.3275911f, ax, 1.0f));
    float p  = fmaf(fmaf(fmaf(fmaf(1.061405429f, t, -1.453152027f), t, 1.421413741f),
                         t, -0.284496736f), t, 0.254829592f);
    float e  = __expf(-ax * ax);
    float er = fmaf(-p * t, e, 1.0f);
    er = copysignf(er, x);
    return 0.5f * v * (1.0f + er);
}

// ---------------- K2: fused per-(b,n) block; 32 warps; half2 conv ----------------
__global__ void __launch_bounds__(NT, 1)
k_fused(const float* __restrict__ x, const float* __restrict__ convw,
        const float* __restrict__ gng, const float* __restrict__ gnb,
        const float* __restrict__ lng, const float* __restrict__ lnb,
        float* __restrict__ out) {
    extern __shared__ char sm[];
    __half* xs   = (__half*)sm;                       // [128][200] halves
    __half* hb   = (__half*)(sm + OFF_HB);            // [128][264] halves
    float* part   = (float*)(sm + OFF_PART);          // [128][8][2] (aliases dead bs)
    float* lnstat = (float*)(sm + OFF_LNSTAT);        // [128][2]
    __shared__ float s_gnx[8][8][2];                  // [group][slice][{s,s2}]
    __shared__ float chA[256], chB[256];

    const int n = blockIdx.x, b = blockIdx.y;
    const int tid  = threadIdx.x;
    const int lane = tid & 31, warp = tid >> 5;
    const int g = lane >> 2, q = lane & 3;
    const int wm = warp & 3, wn = warp >> 2;          // 4 x 8 warp grid; tile 32t x 32c

    const __half* wbase = g_wh + (size_t)n * 512 * CIN;

    const uint32_t xs_u32 = (uint32_t)__cvta_generic_to_shared(xs);
    const uint32_t bs_u32 = xs_u32 + OFF_BS;

    const int a_row_off = (lane & 7) + ((lane >> 3) & 1) * 8;
    const int a_k_off   = ((lane >> 4) & 1) * 8;
    uint32_t addrA[2];
#pragma unroll
    for (int mi = 0; mi < 2; mi++)
        addrA[mi] = xs_u32 + (uint32_t)((wm * 32 + mi * 16 + a_row_off) * (XS_PITCH * 2) + a_k_off * 2);
    const int b_n_off = ((lane >> 4) & 1) * 8 + (lane & 7);
    const int b_k_off = ((lane >> 3) & 1) * 8;
    uint32_t addrB[2];
#pragma unroll
    for (int pp = 0; pp < 2; pp++)
        addrB[pp] = bs_u32 + (uint32_t)((wn * 32 + pp * 16 + b_n_off) * (BS_PITCH * 2) + b_k_off * 2);

    // stage chunk c (0..5): p = c>=3, kcc = c%3, buf = c%3; 2 cp.async per thread
    auto stage = [&](int c) {
        int p = (c >= 3) ? 1 : 0;
        int kcc = c - 3 * p;
        int col = tid >> 2, hv = tid & 3;
        const __half* src = wbase + (size_t)(p * 256 + col) * CIN + kcc * 64 + hv * 16;
        uint32_t d = bs_u32 + (uint32_t)((c % 3) * BS_STAGE + col * (BS_PITCH * 2) + hv * 32);
        cp_async16(d,      src);
        cp_async16(d + 16, src + 8);
        asm volatile("cp.async.commit_group;\n");
    };

    // one GEMM chunk-iteration (leading barrier handled by caller); pp-split to cap live regs
    auto gemm_chunk = [&](int kc, float (*acc)[4][4]) {
        const uint32_t bsel = (uint32_t)((kc % 3) * BS_STAGE);
#pragma unroll
        for (int ks = 0; ks < 4; ks++) {
            const uint32_t kbb = (uint32_t)((kc * 64 + ks * 16) * 2);
            uint32_t afr[2][4];
#pragma unroll
            for (int mi = 0; mi < 2; mi++)
                ldsm_x4(afr[mi][0], afr[mi][1], afr[mi][2], afr[mi][3], addrA[mi] + kbb);
#pragma unroll
            for (int pp = 0; pp < 2; pp++) {
                uint32_t bfr[2][2];
                ldsm_x4(bfr[0][0], bfr[0][1], bfr[1][0], bfr[1][1],
                        addrB[pp] + bsel + (uint32_t)(ks * 32));
#pragma unroll
                for (int nj = 0; nj < 2; nj++)
#pragma unroll
                    for (int mi = 0; mi < 2; mi++)
                        mma16816(acc[mi][pp * 2 + nj], afr[mi], bfr[nj]);
            }
        }
    };

    // ---- prologue: deep prefetch + x load ----
    stage(0);
    stage(1);
    for (int i = tid; i < 128 * 48; i += NT) {
        int t = i / 48, c4 = (i % 48) * 4;
        float4 v = *(const float4*)(x + ((size_t)(b * Tn + t) * Nn + n) * CIN + c4);
        __half2* dst = (__half2*)(xs + t * XS_PITCH + c4);
        dst[0] = __floats2half2_rn(v.x, v.y);
        dst[1] = __floats2half2_rn(v.z, v.w);
    }
    __syncthreads();

    float acc[2][4][4];
#pragma unroll
    for (int mi = 0; mi < 2; mi++)
#pragma unroll
        for (int ni = 0; ni < 4; ni++)
#pragma unroll
            for (int r = 0; r < 4; r++) acc[mi][ni][r] = 0.f;

    // ================= p0 mainloop: chunks 0..2, leading-barrier only =================
#pragma unroll 1
    for (int kc = 0; kc < 3; kc++) {
        if (kc == 0) { stage(2); asm volatile("cp.async.wait_group 2;\n"); }
        else if (kc == 1) { asm volatile("cp.async.wait_group 1;\n"); }
        else { asm volatile("cp.async.wait_group 0;\n"); }
        __syncthreads();
        gemm_chunk(kc, acc);
    }

    // prefetch first p1 chunk (buf 0 free: all warps past iter-2 barrier)
    stage(3);

    // ---- p0 epilogue: h -> fp16 hbuf[t][o] ----
#pragma unroll
    for (int mi = 0; mi < 2; mi++) {
#pragma unroll
        for (int half = 0; half < 2; half++) {
            int t = wm * 32 + mi * 16 + g + half * 8;
            int r = half * 2;
#pragma unroll
            for (int ni = 0; ni < 4; ni++) {
                int o0 = wn * 32 + ni * 8 + 2 * q;
                *(__half2*)(hb + t * HBUF_PITCH + o0) = __floats2half2_rn(acc[mi][ni][r], acc[mi][ni][r + 1]);
            }
        }
    }
    __syncthreads();

    // ---- temporal conv + GN stats; thread = (channel-pair, t-slice of 16); half2 loads ----
    {
        const int o2 = tid & 127, sl = tid >> 7;      // channel pair 2*o2, slice 0..7
        const int c0 = 2 * o2;
        const int ct0 = sl * 16, ct1 = ct0 + 16;
        const float w0a = convw[c0 * 3],     w1a = convw[c0 * 3 + 1], w2a = convw[c0 * 3 + 2];
        const float w0b = convw[c0 * 3 + 3], w1b = convw[c0 * 3 + 4], w2b = convw[c0 * 3 + 5];
        float2 prev = (ct0 == 0) ? make_float2(0.f, 0.f)
                                 : __half22float2(*(const __half2*)(hb + (ct0 - 1) * HBUF_PITCH + c0));
        float2 cur  = __half22float2(*(const __half2*)(hb + ct0 * HBUF_PITCH + c0));
        float2 bnd  = (ct1 == Tn) ? make_float2(0.f, 0.f)
                                  : __half22float2(*(const __half2*)(hb + ct1 * HBUF_PITCH + c0));
        __syncthreads();
        float csA = 0.f, cs2A = 0.f, csB = 0.f, cs2B = 0.f;
#pragma unroll
        for (int t = ct0; t < ct1; t++) {
            float2 nxt = (t == ct1 - 1) ? bnd
                       : __half22float2(*(const __half2*)(hb + (t + 1) * HBUF_PITCH + c0));
            float v0 = w0a * prev.x + w1a * cur.x + w2a * nxt.x;
            float v1 = w0b * prev.y + w1b * cur.y + w2b * nxt.y;
            *(__half2*)(hb + t * HBUF_PITCH + c0) = __floats2half2_rn(v0, v1);
            csA += v0; cs2A += v0 * v0; csB += v1; cs2B += v1 * v1;
            prev = cur; cur = nxt;
        }
        float cs  = csA + csB;       // both channels in same GN group
        float cs2 = cs2A + cs2B;
#pragma unroll
        for (int off = 8; off; off >>= 1) {
            cs  += __shfl_xor_sync(0xFFFFFFFFu, cs,  off);
            cs2 += __shfl_xor_sync(0xFFFFFFFFu, cs2, off);
        }
        if ((lane & 15) == 0) {
            int grp = (warp & 3) * 2 + (lane >> 4);
            s_gnx[grp][warp >> 2][0] = cs;
            s_gnx[grp][warp >> 2][1] = cs2;
        }
    }
    __syncthreads();
    if (tid < 256) {
        const int o = tid, grp = o >> 5;
        float gs = 0.f, gs2 = 0.f;
#pragma unroll
        for (int sl2 = 0; sl2 < 8; sl2++) {
            gs  += s_gnx[grp][sl2][0];
            gs2 += s_gnx[grp][sl2][1];
        }
        const float inv = 1.f / (32.f * Tn);
        float mu = gs * inv;
        float var = gs2 * inv - mu * mu;
        float rstd = rsqrtf(var + 1e-5f);
        float ga = gng[o] * rstd;
        chA[o] = ga;
        chB[o] = gnb[o] - mu * ga;
    }

    // prefetch second p1 chunk during phase transition (buf 1 free)
    stage(4);

    // zero acc for p1
#pragma unroll
    for (int mi = 0; mi < 2; mi++)
#pragma unroll
        for (int ni = 0; ni < 4; ni++)
#pragma unroll
            for (int r = 0; r < 4; r++) acc[mi][ni][r] = 0.f;

    // ================= p1 mainloop: chunks 3..5 =================
#pragma unroll 1
    for (int kc = 0; kc < 3; kc++) {
        if (kc == 0) { stage(5); asm volatile("cp.async.wait_group 2;\n"); }
        else if (kc == 1) { asm volatile("cp.async.wait_group 1;\n"); }
        else { asm volatile("cp.async.wait_group 0;\n"); }
        __syncthreads();
        gemm_chunk(kc, acc);
    }
    __syncthreads();   // bs region about to be reused as part/lnstat

    // ---- fold: v = h*ga + gb + res (in regs) + LN partial sums ----
#pragma unroll
    for (int mi = 0; mi < 2; mi++) {
#pragma unroll
        for (int half = 0; half < 2; half++) {
            int t = wm * 32 + mi * 16 + g + half * 8;
            int r = half * 2;
            float su = 0.f, sq = 0.f;
#pragma unroll
            for (int ni = 0; ni < 4; ni++) {
                int o0 = wn * 32 + ni * 8 + 2 * q;
                float2 hv = __half22float2(*(const __half2*)(hb + t * HBUF_PITCH + o0));
                float v0 = hv.x * chA[o0]     + chB[o0]     + acc[mi][ni][r];
                float v1 = hv.y * chA[o0 + 1] + chB[o0 + 1] + acc[mi][ni][r + 1];
                acc[mi][ni][r] = v0; acc[mi][ni][r + 1] = v1;
                su += v0 + v1; sq += v0 * v0 + v1 * v1;
            }
            su += __shfl_xor_sync(0xFFFFFFFFu, su, 1);
            su += __shfl_xor_sync(0xFFFFFFFFu, su, 2);
            sq += __shfl_xor_sync(0xFFFFFFFFu, sq, 1);
            sq += __shfl_xor_sync(0xFFFFFFFFu, sq, 2);
            if (q == 0) *(float2*)(part + (t * 8 + wn) * 2) = make_float2(su, sq);
        }
    }
    __syncthreads();
    if (tid < Tn) {
        float su = 0.f, sq = 0.f;
#pragma unroll
        for (int w = 0; w < 8; w++) {
            float2 p = *(const float2*)(part + (tid * 8 + w) * 2);
            su += p.x; sq += p.y;
        }
        float mu = su * (1.f / 256.f);
        float var = sq * (1.f / 256.f) - mu * mu;
        *(float2*)(lnstat + tid * 2) = make_float2(mu, rsqrtf(var + 1e-5f));
    }
    __syncthreads();

    // ---- apply LN + GELU, direct store (gamma/beta hoisted) ----
    float2 lg2[4], lb2[4];
#pragma unroll
    for (int ni = 0; ni < 4; ni++) {
        int o0 = wn * 32 + ni * 8 + 2 * q;
        lg2[ni] = *(const float2*)(lng + o0);
        lb2[ni] = *(const float2*)(lnb + o0);
    }
#pragma unroll
    for (int mi = 0; mi < 2; mi++) {
#pragma unroll
        for (int half = 0; half < 2; half++) {
            int t = wm * 32 + mi * 16 + g + half * 8;
            float2 st = *(const float2*)(lnstat + t * 2);
            float mu = st.x, rs = st.y;
            float* ob = out + ((size_t)(b * Tn + t) * Nn + n) * COUT;
            int r = half * 2;
#pragma unroll
            for (int ni = 0; ni < 4; ni++) {
                int o0 = wn * 32 + ni * 8 + 2 * q;
                float y0 = (acc[mi][ni][r]     - mu) * rs * lg2[ni].x + lb2[ni].x;
                float y1 = (acc[mi][ni][r + 1] - mu) * rs * lg2[ni].y + lb2[ni].y;
                *(float2*)(ob + o0) = make_float2(gelu_fast(y0), gelu_fast(y1));
            }
        }
    }
}

// ---------------- launch ----------------
extern "C" void kernel_launch(void* const* d_in, const int* in_sizes, int n_in,
                              void* d_out, int out_size) {
    const float* x     = (const float*)d_in[0];
    const float* A     = (const float*)d_in[1];
    const float* dw    = (const float*)d_in[2];
    const float* adj   = (const float*)d_in[3];
    const float* Wpw   = (const float*)d_in[4];
    const float* convw = (const float*)d_in[5];
    const float* gng   = (const float*)d_in[6];
    const float* gnb   = (const float*)d_in[7];
    const float* lng   = (const float*)d_in[8];
    const float* lnb   = (const float*)d_in[9];
    const float* Wres  = (const float*)d_in[10];
    float* out = (float*)d_out;

    cudaFuncSetAttribute(k_fused, cudaFuncAttributeMaxDynamicSharedMemorySize, SMEM_TOTAL);

    int total8 = Nn * 512 * 24;
    k_wh<<<(total8 + 255) / 256, 256>>>(A, adj, dw, Wpw, Wres);
    k_fused<<<dim3(Nn, Bsz), NT, SMEM_TOTAL>>>(x, convw, gng, gnb, lng, lnb, out);
}